// round 9
// baseline (speedup 1.0000x reference)
#include <cuda_runtime.h>

// Problem constants
#define B_     8
#define DIM    64
#define HID    128
#define HH     192
#define WW     192
#define HW     (HH*WW)          // 36864
#define TS     16
#define PAD    18
#define NPIX   (PAD*PAD)        // 324
#define NTILX  12
#define NTILY  12
#define NTILES (NTILX*NTILY*B_) // 1152
#define NT     256
// Phase-1 register tiling: 11 px x 8 hid-pairs per thread, 240 jobs
#define PXG    11
#define NPXG   30               // 30*11 = 330 >= 324
#define PPT    8
#define P1JOBS (NPXG*8)         // 240
#define XSTR   330              // staged x row stride (pixels)
#define CCH    16               // input channels staged per chunk
#define YCH    8                // phase-2 y-chunk (hid-pairs)

typedef unsigned long long ull;

__device__ __forceinline__ ull ffma2(ull a, ull b, ull c) {
    ull d;
    asm("fma.rn.f32x2 %0, %1, %2, %3;" : "=l"(d) : "l"(a), "l"(b), "l"(c));
    return d;
}
__device__ __forceinline__ ull mul2(ull a, ull b) {
    ull d;
    asm("mul.rn.f32x2 %0, %1, %2;" : "=l"(d) : "l"(a), "l"(b));
    return d;
}
__device__ __forceinline__ ull pack2(float x) {
    ull r;
    asm("mov.b64 %0, {%1, %1};" : "=l"(r) : "f"(x));
    return r;
}
__device__ __forceinline__ ull pack2b(float lo, float hi) {
    ull r;
    asm("mov.b64 %0, {%1, %2};" : "=l"(r) : "f"(lo), "f"(hi));
    return r;
}
__device__ __forceinline__ void unpack2(ull v, float& lo, float& hi) {
    asm("mov.b64 {%0, %1}, %2;" : "=f"(lo), "=f"(hi) : "l"(v));
}

// Scratch + barrier state (zero-initialized; no device mallocs allowed)
__device__ float g_xmean[B_*DIM];
__device__ float g_ker[B_*HID*9];
__device__ unsigned g_bar1, g_bar2, g_done;

__device__ __forceinline__ void gbar(unsigned* bar, unsigned NB, int tid) {
    if (tid == 0) {
        __threadfence();
        atomicAdd(bar, 1u);
        while (atomicAdd(bar, 0u) < NB) __nanosleep(128);
    }
    __syncthreads();
    __threadfence();
}

extern __shared__ float smem[];

// Dynamic SMEM layout (float offsets):
//   sh_w    [0     .. 8192)   phase1: w_in^T [c][hid] / phase2: w_out [hid][o]
//   sh_ker2 [8192  .. 9344)   576 ull paired dyn kernels
//   sh_bin  [9344  .. 9472)
//   sh_bout [9472  .. 9536)
//   sh_stg  [9536  .. 14816)  x-chunk (16c x 330) OR y-chunk (8 pairs x 256 ull)
//   sh_h    [14816 .. 56288)  64 hid-pairs x 324 px (ull)
// total 56288 floats = 225,152 B
__global__ __launch_bounds__(NT, 1)
void k_all(const float* __restrict__ x,
           const float* __restrict__ w_in,  const float* __restrict__ b_in,
           const float* __restrict__ wg1,   const float* __restrict__ bg1,
           const float* __restrict__ wg2,   const float* __restrict__ bg2,
           const float* __restrict__ w_out, const float* __restrict__ b_out,
           float* __restrict__ out) {
    const int tid = threadIdx.x;
    const unsigned NB = gridDim.x;

    // =================== Phase A: per-(b,c) spatial means ===================
    {
        __shared__ float redw[8];
        for (int bc = blockIdx.x; bc < B_*DIM; bc += (int)NB) {
            const float4* p = (const float4*)(x + (size_t)bc * HW);
            float s = 0.f;
            #pragma unroll 4
            for (int i = tid; i < HW/4; i += NT) {
                float4 v = p[i];
                s += (v.x + v.y) + (v.z + v.w);
            }
            #pragma unroll
            for (int o = 16; o; o >>= 1) s += __shfl_down_sync(0xffffffffu, s, o);
            if ((tid & 31) == 0) redw[tid >> 5] = s;
            __syncthreads();
            if (tid < 32) {
                s = (tid < 8) ? redw[tid] : 0.f;
                #pragma unroll
                for (int o = 4; o; o >>= 1) s += __shfl_down_sync(0xffffffffu, s, o);
                if (tid == 0) g_xmean[bc] = s * (1.0f / (float)HW);
            }
            __syncthreads();
        }
    }
    gbar(&g_bar1, NB, tid);

    // =================== Phase B: dynamic kernel generation =================
    if (blockIdx.x < B_) {
        const int b = blockIdx.x;
        __shared__ float xm[DIM], g0[HID], g1[HID];
        if (tid < DIM) xm[tid] = g_xmean[b*DIM + tid];
        __syncthreads();
        if (tid < HID) {
            float s = b_in[tid];
            #pragma unroll 8
            for (int c = 0; c < DIM; c++) s = fmaf(w_in[tid*DIM + c], xm[c], s);
            g0[tid] = s;   // == spatial mean of h[b, tid] (mean is linear)
        }
        __syncthreads();
        if (tid < HID) {
            float s = bg1[tid];
            #pragma unroll 8
            for (int c = 0; c < HID; c++) s = fmaf(wg1[tid*HID + c], g0[c], s);
            g1[tid] = s > 0.f ? s : 0.f;
        }
        __syncthreads();
        if (tid < HID) {
            #pragma unroll
            for (int tt = 0; tt < 9; tt++) {
                int row = tid*9 + tt;
                float s = bg2[row];
                #pragma unroll 8
                for (int c = 0; c < HID; c++) s = fmaf(wg2[row*HID + c], g1[c], s);
                g_ker[b*HID*9 + row] = s;
            }
        }
    }
    gbar(&g_bar2, NB, tid);

    // ======================= Phase C: fused main loop =======================
    float* sh_w    = smem;
    ull*   sh_ker2 = (ull*)(smem + 8192);
    float* sh_bin  = smem + 9344;
    float* sh_bout = smem + 9472;
    float* sh_stg  = smem + 9536;
    ull*   sh_y    = (ull*)sh_stg;
    ull*   sh_h    = (ull*)(smem + 14816);
    const ull* sh_wull = (const ull*)smem;

    if (tid < HID) sh_bin[tid]  = b_in[tid];
    if (tid < 64)  sh_bout[tid] = b_out[tid];

    // phase-1 job decode (tid < P1JOBS active)
    const int pxg = tid >> 3;        // 0..31 (30 used)
    const int pb  = tid & 7;
    const int px0 = pxg * PXG;
    // phase-2b decode
    const int pxq = tid >> 2;        // 0..63
    const int ob  = tid & 3;

    const ull ABSM = 0x7fffffff7fffffffULL;
    const ull C55 = pack2(0.55f), C45 = pack2(0.45f);

    #pragma unroll 1
    for (int t = blockIdx.x; t < NTILES; t += (int)NB) {
        const int b   = t / (NTILX*NTILY);
        const int r   = t - b*(NTILX*NTILY);
        const int ty0 = (r / NTILX)*TS;
        const int tx0 = (r % NTILX)*TS;
        const float* xb = x + (size_t)b * DIM * HW;

        __syncthreads();   // previous tile finished reading sh_w / sh_h

        // stage w_in^T [c][hid] + this sample's paired kernels
        for (int i = tid; i < HID*DIM; i += NT) {
            int o = i >> 6, c = i & 63;
            sh_w[c*HID + o] = w_in[i];
        }
        {
            const float* kb = g_ker + b*HID*9;
            for (int i = tid; i < 64*9; i += NT) {
                int p = i / 9, tt = i - p*9;
                sh_ker2[i] = pack2b(kb[(2*p)*9 + tt], kb[(2*p+1)*9 + tt]);
            }
        }
        __syncthreads();

        // --------------- Phase 1: h GEMM, register-blocked 11x8 -------------
        ull acc[PXG][PPT];
        if (tid < P1JOBS) {
            const ull* bp = (const ull*)sh_bin + pb*PPT;
            ull bseg[PPT];
            #pragma unroll
            for (int j = 0; j < PPT; j++) bseg[j] = bp[j];
            #pragma unroll
            for (int k = 0; k < PXG; k++)
                #pragma unroll
                for (int j = 0; j < PPT; j++) acc[k][j] = bseg[j];
        }

        #pragma unroll 1
        for (int cc = 0; cc < DIM; cc += CCH) {
            // stage x chunk [16 c][330 px] with border zeros
            for (int i = tid; i < CCH*XSTR; i += NT) {
                int c  = i / XSTR, pp = i - c*XSTR;
                float v = 0.f;
                if (pp < NPIX) {
                    int py = pp / PAD, pxx = pp - py*PAD;
                    int gy = ty0 + py - 1, gx = tx0 + pxx - 1;
                    if ((gy >= 0) & (gy < HH) & (gx >= 0) & (gx < WW))
                        v = __ldg(xb + (size_t)(cc + c)*HW + gy*WW + gx);
                }
                sh_stg[i] = v;
            }
            __syncthreads();

            if (tid < P1JOBS) {
                #pragma unroll 1
                for (int c = 0; c < CCH; c++) {
                    const float* xs = sh_stg + c*XSTR + px0;
                    const ulonglong2* wp =
                        (const ulonglong2*)(sh_wull + (size_t)(cc + c)*64 + pb*PPT);
                    ulonglong2 wA = wp[0], wB = wp[1], wC = wp[2], wD = wp[3];
                    #pragma unroll
                    for (int k = 0; k < PXG; k++) {
                        ull xx = pack2(xs[k]);
                        acc[k][0] = ffma2(wA.x, xx, acc[k][0]);
                        acc[k][1] = ffma2(wA.y, xx, acc[k][1]);
                        acc[k][2] = ffma2(wB.x, xx, acc[k][2]);
                        acc[k][3] = ffma2(wB.y, xx, acc[k][3]);
                        acc[k][4] = ffma2(wC.x, xx, acc[k][4]);
                        acc[k][5] = ffma2(wC.y, xx, acc[k][5]);
                        acc[k][6] = ffma2(wD.x, xx, acc[k][6]);
                        acc[k][7] = ffma2(wD.y, xx, acc[k][7]);
                    }
                }
            }
            __syncthreads();   // before next chunk overwrites sh_stg
        }

        // store h (zero-masked at borders) + restage sh_w -> w_out [hid][o]
        if (tid < P1JOBS) {
            #pragma unroll
            for (int k = 0; k < PXG; k++) {
                int pp = px0 + k;
                if (pp < NPIX) {
                    int py = pp / PAD, pxx = pp - py*PAD;
                    int gy = ty0 + py - 1, gx = tx0 + pxx - 1;
                    bool v = (gy >= 0) & (gy < HH) & (gx >= 0) & (gx < WW);
                    #pragma unroll
                    for (int j = 0; j < PPT; j++)
                        sh_h[(pb*PPT + j)*NPIX + pp] = v ? acc[k][j] : 0ull;
                }
            }
        }
        __syncthreads();
        for (int i = tid; i < 64*HID; i += NT) {
            int o = i >> 7, hid = i & 127;
            sh_w[hid*64 + o] = w_out[i];
        }
        __syncthreads();

        // --------------- Phase 2: dw+leaky (2a) then projection (2b) -------
        ull pacc[4][8];
        {
            const ull* bop = (const ull*)sh_bout + ob*8;
            ull bs[8];
            #pragma unroll
            for (int j = 0; j < 8; j++) bs[j] = bop[j];
            #pragma unroll
            for (int k = 0; k < 4; k++)
                #pragma unroll
                for (int j = 0; j < 8; j++) pacc[k][j] = bs[j];
        }

        #pragma unroll 1
        for (int yc = 0; yc < 64; yc += YCH) {
            // 2a: y for pairs [yc, yc+8) over the 256 interior pixels
            #pragma unroll 1
            for (int s = 0; s < 8; s++) {
                int slot = tid + s*NT;           // 0..2047
                int p  = slot >> 8;              // 0..7
                int px = slot & 255;
                int ix = px & 15, iy = px >> 4;
                int ctr = (iy + 1)*PAD + ix + 1;
                int gp  = yc + p;
                const ull* hp = sh_h + gp*NPIX + ctr;
                const ull* kp = sh_ker2 + gp*9;
                ull sa;
                sa = mul2 (kp[0], hp[-PAD-1]);
                sa = ffma2(kp[1], hp[-PAD  ], sa);
                sa = ffma2(kp[2], hp[-PAD+1], sa);
                sa = ffma2(kp[3], hp[-1    ], sa);
                sa = ffma2(kp[4], hp[ 0    ], sa);
                sa = ffma2(kp[5], hp[ 1    ], sa);
                sa = ffma2(kp[6], hp[ PAD-1], sa);
                sa = ffma2(kp[7], hp[ PAD  ], sa);
                sa = ffma2(kp[8], hp[ PAD+1], sa);
                // LeakyReLU(0.1) packed: 0.55*s + 0.45*|s|
                sh_y[p*256 + px] = ffma2(sa & ABSM, C45, mul2(sa, C55));
            }
            __syncthreads();

            // 2b: projection, thread tile 4 px x 8 out-pairs
            #pragma unroll 2
            for (int p = 0; p < YCH; p++) {
                int gp = yc + p;
                const ulonglong2* yp = (const ulonglong2*)(sh_y + p*256 + pxq*4);
                ulonglong2 ya = yp[0], yb2 = yp[1];
                ull yv[4] = {ya.x, ya.y, yb2.x, yb2.y};
                const ulonglong2* wl = (const ulonglong2*)(sh_wull + (size_t)gp*64 + ob*8);
                const ulonglong2* wh = (const ulonglong2*)(sh_wull + (size_t)gp*64 + 32 + ob*8);
                ulonglong2 l01 = wl[0], l23 = wl[1], l45 = wl[2], l67 = wl[3];
                ulonglong2 h01 = wh[0], h23 = wh[1], h45 = wh[2], h67 = wh[3];
                ull wlo[8] = {l01.x, l01.y, l23.x, l23.y, l45.x, l45.y, l67.x, l67.y};
                ull whi[8] = {h01.x, h01.y, h23.x, h23.y, h45.x, h45.y, h67.x, h67.y};
                #pragma unroll
                for (int k = 0; k < 4; k++) {
                    float ylo, yhi;
                    unpack2(yv[k], ylo, yhi);
                    ull ylo2 = pack2(ylo), yhi2 = pack2(yhi);
                    #pragma unroll
                    for (int j = 0; j < 8; j++) {
                        pacc[k][j] = ffma2(wlo[j], ylo2, pacc[k][j]);
                        pacc[k][j] = ffma2(whi[j], yhi2, pacc[k][j]);
                    }
                }
            }
            __syncthreads();   // before next chunk overwrites sh_y
        }

        // store output: 4 px x 16 out-channels per thread
        {
            #pragma unroll
            for (int k = 0; k < 4; k++) {
                int px = pxq*4 + k;
                int ix = px & 15, iy = px >> 4;
                int gy = ty0 + iy, gx = tx0 + ix;
                float* op = out + (size_t)b * DIM * HW + gy*WW + gx;
                #pragma unroll
                for (int j = 0; j < 8; j++) {
                    int och = ob*16 + 2*j;
                    float lo, hi;
                    unpack2(pacc[k][j], lo, hi);
                    op[(size_t)och * HW]       = lo;
                    op[(size_t)(och + 1) * HW] = hi;
                }
            }
        }
    }

    // reset barrier state for the next graph replay
    if (tid == 0) {
        __threadfence();
        if (atomicAdd(&g_done, 1u) == NB - 1u) {
            atomicExch(&g_bar1, 0u);
            atomicExch(&g_bar2, 0u);
            atomicExch(&g_done, 0u);
        }
    }
}

// ---------------------------------------------------------------------------
extern "C" void kernel_launch(void* const* d_in, const int* in_sizes, int n_in,
                              void* d_out, int out_size) {
    const float* x     = (const float*)d_in[0];
    const float* w_in  = (const float*)d_in[1];
    const float* b_in  = (const float*)d_in[2];
    const float* wg1   = (const float*)d_in[3];
    const float* bg1   = (const float*)d_in[4];
    const float* wg2   = (const float*)d_in[5];
    const float* bg2   = (const float*)d_in[6];
    const float* w_out = (const float*)d_in[7];
    const float* b_out = (const float*)d_in[8];
    float* out = (float*)d_out;

    int dev = 0, nsm = 148;
    cudaGetDevice(&dev);
    cudaDeviceGetAttribute(&nsm, cudaDevAttrMultiProcessorCount, dev);

    const int SMEM_BYTES = 56288 * 4;   // 225,152 B
    cudaFuncSetAttribute(k_all, cudaFuncAttributeMaxDynamicSharedMemorySize, SMEM_BYTES);

    k_all<<<nsm, NT, SMEM_BYTES>>>(x, w_in, b_in, wg1, bg1, wg2, bg2, w_out, b_out, out);
}

// round 10
// speedup vs baseline: 1.5663x; 1.5663x over previous
#include <cuda_runtime.h>

// Problem constants
#define B_     8
#define DIM    64
#define HID    128
#define HH     192
#define WW     192
#define HW     (HH*WW)
#define TS     16
#define PAD    18
#define NPIX   324
#define NTILX  12
#define NTILY  12
#define NTILES 1152
#define NT     256

// SMEM float offsets
#define OF_WINT 0          // 8192: w_in^T [c][128]
#define OF_WOUT 8192       // 8192: w_out [hid][64]
#define OF_KER2 16384      // 1152: 576 ull paired dyn kernels
#define OF_BIN  17536      // 128
#define OF_BOUT 17664      // 64
#define OF_X    17728      // 10368: x chunk [32c][324]
#define OF_Y    28096      // 4096: y chunk (8 pairs x 256 ull)
#define OF_H    32192      // 20736: h half (32 pairs x 324 ull)
#define SM_FLOATS 52928    // 211,712 B

typedef unsigned long long ull;

__device__ __forceinline__ ull ffma2(ull a, ull b, ull c) {
    ull d;
    asm("fma.rn.f32x2 %0, %1, %2, %3;" : "=l"(d) : "l"(a), "l"(b), "l"(c));
    return d;
}
__device__ __forceinline__ ull mul2(ull a, ull b) {
    ull d;
    asm("mul.rn.f32x2 %0, %1, %2;" : "=l"(d) : "l"(a), "l"(b));
    return d;
}
__device__ __forceinline__ ull pack2(float x) {
    ull r;
    asm("mov.b64 %0, {%1, %1};" : "=l"(r) : "f"(x));
    return r;
}
__device__ __forceinline__ ull pack2b(float lo, float hi) {
    ull r;
    asm("mov.b64 %0, {%1, %2};" : "=l"(r) : "f"(lo), "f"(hi));
    return r;
}
__device__ __forceinline__ void unpack2(ull v, float& lo, float& hi) {
    asm("mov.b64 {%0, %1}, %2;" : "=f"(lo), "=f"(hi) : "l"(v));
}

// Scratch + barrier state (zero-initialized; no device mallocs allowed)
__device__ float g_xmean[B_*DIM];
__device__ float g_ker[B_*HID*9];
__device__ unsigned g_bar1, g_bar2, g_done;

__device__ __forceinline__ void gbar(unsigned* bar, unsigned NB, int tid) {
    if (tid == 0) {
        __threadfence();
        atomicAdd(bar, 1u);
        while (atomicAdd(bar, 0u) < NB) __nanosleep(128);
    }
    __syncthreads();
    __threadfence();
}

extern __shared__ float smem[];

__global__ __launch_bounds__(NT, 1)
void k_all(const float* __restrict__ x,
           const float* __restrict__ w_in,  const float* __restrict__ b_in,
           const float* __restrict__ wg1,   const float* __restrict__ bg1,
           const float* __restrict__ wg2,   const float* __restrict__ bg2,
           const float* __restrict__ w_out, const float* __restrict__ b_out,
           float* __restrict__ out) {
    const int tid = threadIdx.x;
    const unsigned NB = gridDim.x;

    // =================== Phase A: per-(b,c) spatial means ===================
    {
        __shared__ float redw[8];
        for (int bc = blockIdx.x; bc < B_*DIM; bc += (int)NB) {
            const float4* p = (const float4*)(x + (size_t)bc * HW);
            float s = 0.f;
            #pragma unroll 4
            for (int i = tid; i < HW/4; i += NT) {
                float4 v = p[i];
                s += (v.x + v.y) + (v.z + v.w);
            }
            #pragma unroll
            for (int o = 16; o; o >>= 1) s += __shfl_down_sync(0xffffffffu, s, o);
            if ((tid & 31) == 0) redw[tid >> 5] = s;
            __syncthreads();
            if (tid < 32) {
                s = (tid < 8) ? redw[tid] : 0.f;
                #pragma unroll
                for (int o = 4; o; o >>= 1) s += __shfl_down_sync(0xffffffffu, s, o);
                if (tid == 0) g_xmean[bc] = s * (1.0f / (float)HW);
            }
            __syncthreads();
        }
    }
    gbar(&g_bar1, NB, tid);

    // =================== Phase B: dynamic kernel generation =================
    if (blockIdx.x < B_) {
        const int b = blockIdx.x;
        __shared__ float xm[DIM], g0[HID], g1[HID];
        if (tid < DIM) xm[tid] = g_xmean[b*DIM + tid];
        __syncthreads();
        if (tid < HID) {
            float s = b_in[tid];
            #pragma unroll 8
            for (int c = 0; c < DIM; c++) s = fmaf(w_in[tid*DIM + c], xm[c], s);
            g0[tid] = s;   // spatial mean of h (mean is linear)
        }
        __syncthreads();
        if (tid < HID) {
            float s = bg1[tid];
            #pragma unroll 8
            for (int c = 0; c < HID; c++) s = fmaf(wg1[tid*HID + c], g0[c], s);
            g1[tid] = s > 0.f ? s : 0.f;
        }
        __syncthreads();
        if (tid < HID) {
            #pragma unroll
            for (int tt = 0; tt < 9; tt++) {
                int row = tid*9 + tt;
                float s = bg2[row];
                #pragma unroll 8
                for (int c = 0; c < HID; c++) s = fmaf(wg2[row*HID + c], g1[c], s);
                g_ker[b*HID*9 + row] = s;
            }
        }
    }
    gbar(&g_bar2, NB, tid);

    // ============== one-time staging of weights + biases ====================
    for (int i = tid; i < HID*DIM; i += NT) {
        int o = i >> 6, c = i & 63;
        smem[OF_WINT + c*HID + o] = w_in[i];      // [c][hid]
    }
    for (int i = tid; i < 64*HID; i += NT) {
        int o = i >> 7, hid = i & 127;
        smem[OF_WOUT + hid*64 + o] = w_out[i];    // [hid][o]
    }
    if (tid < HID) smem[OF_BIN + tid]  = b_in[tid];
    if (tid < 64)  smem[OF_BOUT + tid] = b_out[tid];

    // ------------------- thread decodes -------------------
    const int pxg = tid >> 2;             // phase1 px-group (0..63, 54 used)
    const int pb  = tid & 3;              // phase1 pairblock (8 pairs)
    const int px0 = pxg * 6;
    const int lane2a = tid & 127;
    const int pg2a   = tid >> 7;          // 0/1
    const int px0a   = lane2a * 2;        // even pixel, pair of px
    const int ctr2a  = ((px0a >> 4) + 1)*PAD + (px0a & 15) + 1;
    const int pxq  = tid >> 2;            // phase2b px-quad (0..63)
    const int ob   = tid & 3;             // phase2b out-pair block (8 pairs)
    const int px0b = pxq * 4;

    const ull ABSM = 0x7fffffff7fffffffULL;
    const ull C55 = pack2(0.55f), C45 = pack2(0.45f);

    #pragma unroll 1
    for (int t = blockIdx.x; t < NTILES; t += (int)NB) {
        const int b   = t / (NTILX*NTILY);
        const int r   = t - b*(NTILX*NTILY);
        const int ty0 = (r / NTILX)*TS;
        const int tx0 = (r % NTILX)*TS;
        const float* xb = x + (size_t)b * DIM * HW;

        __syncthreads();   // prior tile done reading sh_ker2 / sh_y / sh_h

        // restage this sample's paired kernels (only b-dependent smem data)
        {
            const float* kb = g_ker + b*HID*9;
            for (int i = tid; i < 64*9; i += NT) {
                int p = i / 9, tt = i - p*9;
                ((ull*)(smem + OF_KER2))[i] = pack2b(kb[(2*p)*9 + tt], kb[(2*p+1)*9 + tt]);
            }
        }

        #pragma unroll 1
        for (int hh = 0; hh < 2; hh++) {
            // ================= Phase 1: h half (32 pairs) =================
            ull acc[6][8];
            {
                const ull* bp = (const ull*)(smem + OF_BIN) + hh*32 + pb*8;
                #pragma unroll
                for (int j = 0; j < 8; j++) {
                    ull bj = bp[j];
                    #pragma unroll
                    for (int k = 0; k < 6; k++) acc[k][j] = bj;
                }
            }

            #pragma unroll 1
            for (int cc = 0; cc < 2; cc++) {
                __syncthreads();   // prior sh_x readers done (also orders ker2)
                // stage x chunk [32c][324px] with border zeros
                for (int i = tid; i < 32*NPIX; i += NT) {
                    int c  = i / NPIX, pp = i - c*NPIX;
                    int py = pp / PAD, pxx = pp - py*PAD;
                    int gy = ty0 + py - 1, gx = tx0 + pxx - 1;
                    float v = 0.f;
                    if ((gy >= 0) & (gy < HH) & (gx >= 0) & (gx < WW))
                        v = __ldg(xb + (size_t)(cc*32 + c)*HW + gy*WW + gx);
                    smem[OF_X + i] = v;
                }
                __syncthreads();

                if (tid < 216) {
                    #pragma unroll 2
                    for (int c = 0; c < 32; c++) {
                        const ulonglong2* wp = (const ulonglong2*)
                            ((const ull*)smem + (size_t)(cc*32 + c)*64 + hh*32 + pb*8);
                        ulonglong2 wA = wp[0], wB = wp[1], wC = wp[2], wD = wp[3];
                        const float* xs = smem + OF_X + c*NPIX + px0;
                        #pragma unroll
                        for (int k = 0; k < 6; k++) {
                            ull xx = pack2(xs[k]);
                            acc[k][0] = ffma2(wA.x, xx, acc[k][0]);
                            acc[k][1] = ffma2(wA.y, xx, acc[k][1]);
                            acc[k][2] = ffma2(wB.x, xx, acc[k][2]);
                            acc[k][3] = ffma2(wB.y, xx, acc[k][3]);
                            acc[k][4] = ffma2(wC.x, xx, acc[k][4]);
                            acc[k][5] = ffma2(wC.y, xx, acc[k][5]);
                            acc[k][6] = ffma2(wD.x, xx, acc[k][6]);
                            acc[k][7] = ffma2(wD.y, xx, acc[k][7]);
                        }
                    }
                }
            }

            // store h half (zero-masked at borders)
            if (tid < 216) {
                #pragma unroll
                for (int k = 0; k < 6; k++) {
                    int pp = px0 + k;
                    int py = pp / PAD, pxx = pp - py*PAD;
                    int gy = ty0 + py - 1, gx = tx0 + pxx - 1;
                    bool v = (gy >= 0) & (gy < HH) & (gx >= 0) & (gx < WW);
                    ull* hd = (ull*)(smem + OF_H) + pb*8*NPIX + pp;
                    #pragma unroll
                    for (int j = 0; j < 8; j++)
                        hd[j*NPIX] = v ? acc[k][j] : 0ull;
                }
            }
            __syncthreads();

            // ================= Phase 2: dw + leaky + projection ============
            ull pacc[4][8];
            if (hh == 0) {
                const ull* bop = (const ull*)(smem + OF_BOUT) + ob*8;
                #pragma unroll
                for (int j = 0; j < 8; j++) {
                    ull bj = bop[j];
                    #pragma unroll
                    for (int k = 0; k < 4; k++) pacc[k][j] = bj;
                }
            } else {
                #pragma unroll
                for (int j = 0; j < 8; j++)
                    #pragma unroll
                    for (int k = 0; k < 4; k++) pacc[k][j] = 0ull;
            }

            #pragma unroll 1
            for (int yc = 0; yc < 32; yc += 8) {
                // 2a: dw 3x3 + LeakyReLU for 8 pairs, 2 px per thread
                #pragma unroll
                for (int s = 0; s < 4; s++) {
                    int p_rel = yc + s*2 + pg2a;
                    int gp = hh*32 + p_rel;
                    const ull* hp = (const ull*)(smem + OF_H) + p_rel*NPIX + ctr2a;
                    const ull* kp = (const ull*)(smem + OF_KER2) + gp*9;
                    ull k0 = kp[0], k1 = kp[1], k2 = kp[2], k3 = kp[3], k4 = kp[4],
                        k5 = kp[5], k6 = kp[6], k7 = kp[7], k8 = kp[8];
                    ull a0 = hp[-PAD-1], a1 = hp[-PAD], a2 = hp[-PAD+1], a3 = hp[-PAD+2];
                    ull b0 = hp[-1],     b1 = hp[0],    b2 = hp[1],      b3 = hp[2];
                    ull c0 = hp[PAD-1],  c1 = hp[PAD],  c2 = hp[PAD+1],  c3 = hp[PAD+2];
                    ull sA = mul2(k0, a0);
                    sA = ffma2(k1, a1, sA); sA = ffma2(k2, a2, sA);
                    sA = ffma2(k3, b0, sA); sA = ffma2(k4, b1, sA); sA = ffma2(k5, b2, sA);
                    sA = ffma2(k6, c0, sA); sA = ffma2(k7, c1, sA); sA = ffma2(k8, c2, sA);
                    ull sB = mul2(k0, a1);
                    sB = ffma2(k1, a2, sB); sB = ffma2(k2, a3, sB);
                    sB = ffma2(k3, b1, sB); sB = ffma2(k4, b2, sB); sB = ffma2(k5, b3, sB);
                    sB = ffma2(k6, c1, sB); sB = ffma2(k7, c2, sB); sB = ffma2(k8, c3, sB);
                    // LeakyReLU(0.1): 0.55*s + 0.45*|s|
                    ulonglong2 yv2;
                    yv2.x = ffma2(sA & ABSM, C45, mul2(sA, C55));
                    yv2.y = ffma2(sB & ABSM, C45, mul2(sB, C55));
                    *(ulonglong2*)((ull*)(smem + OF_Y) + (p_rel - yc)*256 + px0a) = yv2;
                }
                __syncthreads();

                // 2b: projection, 4 px x 8 out-pairs per thread
                #pragma unroll 1
                for (int p = 0; p < 8; p++) {
                    int gp = hh*32 + yc + p;
                    const ulonglong2* yp =
                        (const ulonglong2*)((const ull*)(smem + OF_Y) + p*256 + px0b);
                    ulonglong2 y01 = yp[0], y23 = yp[1];
                    const ull* wbase = (const ull*)(smem + OF_WOUT);
                    const ulonglong2* wl =
                        (const ulonglong2*)(wbase + (size_t)(2*gp)*32 + ob*8);
                    const ulonglong2* wh =
                        (const ulonglong2*)(wbase + (size_t)(2*gp)*32 + 32 + ob*8);
                    ulonglong2 l01 = wl[0], l23 = wl[1], l45 = wl[2], l67 = wl[3];
                    ulonglong2 h01 = wh[0], h23 = wh[1], h45 = wh[2], h67 = wh[3];
                    ull wlo[8] = {l01.x, l01.y, l23.x, l23.y, l45.x, l45.y, l67.x, l67.y};
                    ull whi[8] = {h01.x, h01.y, h23.x, h23.y, h45.x, h45.y, h67.x, h67.y};
                    ull yv[4] = {y01.x, y01.y, y23.x, y23.y};
                    #pragma unroll
                    for (int k = 0; k < 4; k++) {
                        float ylo, yhi;
                        unpack2(yv[k], ylo, yhi);
                        ull ylo2 = pack2(ylo), yhi2 = pack2(yhi);
                        #pragma unroll
                        for (int j = 0; j < 8; j++) {
                            pacc[k][j] = ffma2(wlo[j], ylo2, pacc[k][j]);
                            pacc[k][j] = ffma2(whi[j], yhi2, pacc[k][j]);
                        }
                    }
                }
                __syncthreads();   // before next yc overwrites sh_y
            }

            // accumulate halves through gmem: hh=0 store, hh=1 read-add-write
            {
                const int gy = ty0 + (px0b >> 4), gx = tx0 + (px0b & 15);
                float* op = out + (size_t)b * DIM * HW + (size_t)gy*WW + gx;
                #pragma unroll
                for (int j = 0; j < 8; j++) {
                    float l0, h0, l1, h1, l2, h2, l3, h3;
                    unpack2(pacc[0][j], l0, h0);
                    unpack2(pacc[1][j], l1, h1);
                    unpack2(pacc[2][j], l2, h2);
                    unpack2(pacc[3][j], l3, h3);
                    float4 vlo = {l0, l1, l2, l3};
                    float4 vhi = {h0, h1, h2, h3};
                    float4* plo = (float4*)(op + (size_t)(ob*16 + 2*j)*HW);
                    float4* phi = (float4*)(op + (size_t)(ob*16 + 2*j + 1)*HW);
                    if (hh == 0) {
                        *plo = vlo;
                        *phi = vhi;
                    } else {
                        float4 rl = *plo, rh = *phi;
                        rl.x += vlo.x; rl.y += vlo.y; rl.z += vlo.z; rl.w += vlo.w;
                        rh.x += vhi.x; rh.y += vhi.y; rh.z += vhi.z; rh.w += vhi.w;
                        *plo = rl;
                        *phi = rh;
                    }
                }
            }
        } // hh
    } // tiles

    // reset barrier state for the next graph replay
    if (tid == 0) {
        __threadfence();
        if (atomicAdd(&g_done, 1u) == NB - 1u) {
            atomicExch(&g_bar1, 0u);
            atomicExch(&g_bar2, 0u);
            atomicExch(&g_done, 0u);
        }
    }
}

// ---------------------------------------------------------------------------
extern "C" void kernel_launch(void* const* d_in, const int* in_sizes, int n_in,
                              void* d_out, int out_size) {
    const float* x     = (const float*)d_in[0];
    const float* w_in  = (const float*)d_in[1];
    const float* b_in  = (const float*)d_in[2];
    const float* wg1   = (const float*)d_in[3];
    const float* bg1   = (const float*)d_in[4];
    const float* wg2   = (const float*)d_in[5];
    const float* bg2   = (const float*)d_in[6];
    const float* w_out = (const float*)d_in[7];
    const float* b_out = (const float*)d_in[8];
    float* out = (float*)d_out;

    int dev = 0, nsm = 148;
    cudaGetDevice(&dev);
    cudaDeviceGetAttribute(&nsm, cudaDevAttrMultiProcessorCount, dev);

    const int SMEM_BYTES = SM_FLOATS * 4;   // 211,712 B
    cudaFuncSetAttribute(k_all, cudaFuncAttributeMaxDynamicSharedMemorySize, SMEM_BYTES);

    k_all<<<nsm, NT, SMEM_BYTES>>>(x, w_in, b_in, wg1, bg1, wg2, bg2, w_out, b_out, out);
}

// round 11
// speedup vs baseline: 1.5979x; 1.0202x over previous
#include <cuda_runtime.h>

// Problem constants
#define B_     8
#define DIM    64
#define HID    128
#define HH     192
#define WW     192
#define HW     (HH*WW)
#define TS     16
#define PAD    18
#define NPIX   324
#define NTILX  12
#define NTILY  12
#define NTILES 1152
#define NT     512

// SMEM float offsets
#define OF_WINT 0          // 8192: w_in^T [c][128]
#define OF_WOUT 8192       // 8192: w_out [hid][64]
#define OF_KER2 16384      // 1152: 576 ull paired dyn kernels
#define OF_BIN  17536      // 128
#define OF_BOUT 17664      // 64
#define OF_X    17728      // 10368: x chunk [32c][324]
#define OF_Y    28096      // 4096: y chunk (8 pairs x 256 ull)
#define OF_H    32192      // 20736: h half (32 pairs x 324 ull)
#define SM_FLOATS 52928    // 211,712 B

typedef unsigned long long ull;

__device__ __forceinline__ ull ffma2(ull a, ull b, ull c) {
    ull d;
    asm("fma.rn.f32x2 %0, %1, %2, %3;" : "=l"(d) : "l"(a), "l"(b), "l"(c));
    return d;
}
__device__ __forceinline__ ull mul2(ull a, ull b) {
    ull d;
    asm("mul.rn.f32x2 %0, %1, %2;" : "=l"(d) : "l"(a), "l"(b));
    return d;
}
__device__ __forceinline__ ull pack2(float x) {
    ull r;
    asm("mov.b64 %0, {%1, %1};" : "=l"(r) : "f"(x));
    return r;
}
__device__ __forceinline__ ull pack2b(float lo, float hi) {
    ull r;
    asm("mov.b64 %0, {%1, %2};" : "=l"(r) : "f"(lo), "f"(hi));
    return r;
}
__device__ __forceinline__ void unpack2(ull v, float& lo, float& hi) {
    asm("mov.b64 {%0, %1}, %2;" : "=f"(lo), "=f"(hi) : "l"(v));
}

// Scratch + barrier state (zero-initialized; no device mallocs allowed)
__device__ float g_xmean[B_*DIM];
__device__ float g_ker[B_*HID*9];
__device__ unsigned g_bar1, g_bar2, g_done;

__device__ __forceinline__ void gbar(unsigned* bar, unsigned NB, int tid) {
    if (tid == 0) {
        __threadfence();
        atomicAdd(bar, 1u);
        while (atomicAdd(bar, 0u) < NB) __nanosleep(128);
    }
    __syncthreads();
    __threadfence();
}

extern __shared__ float smem[];

__global__ __launch_bounds__(NT, 1)
void k_all(const float* __restrict__ x,
           const float* __restrict__ w_in,  const float* __restrict__ b_in,
           const float* __restrict__ wg1,   const float* __restrict__ bg1,
           const float* __restrict__ wg2,   const float* __restrict__ bg2,
           const float* __restrict__ w_out, const float* __restrict__ b_out,
           float* __restrict__ out) {
    const int tid = threadIdx.x;
    const unsigned NB = gridDim.x;

    // =================== Phase A: per-(b,c) spatial means ===================
    {
        __shared__ float redw[16];
        for (int bc = blockIdx.x; bc < B_*DIM; bc += (int)NB) {
            const float4* p = (const float4*)(x + (size_t)bc * HW);
            float s = 0.f;
            #pragma unroll 4
            for (int i = tid; i < HW/4; i += NT) {
                float4 v = p[i];
                s += (v.x + v.y) + (v.z + v.w);
            }
            #pragma unroll
            for (int o = 16; o; o >>= 1) s += __shfl_down_sync(0xffffffffu, s, o);
            if ((tid & 31) == 0) redw[tid >> 5] = s;
            __syncthreads();
            if (tid < 32) {
                s = (tid < 16) ? redw[tid] : 0.f;
                #pragma unroll
                for (int o = 8; o; o >>= 1) s += __shfl_down_sync(0xffffffffu, s, o);
                if (tid == 0) g_xmean[bc] = s * (1.0f / (float)HW);
            }
            __syncthreads();
        }
    }
    gbar(&g_bar1, NB, tid);

    // =================== Phase B: dynamic kernel generation =================
    if (blockIdx.x < B_) {
        const int b = blockIdx.x;
        __shared__ float xm[DIM], g0[HID], g1[HID];
        if (tid < DIM) xm[tid] = g_xmean[b*DIM + tid];
        __syncthreads();
        if (tid < HID) {
            float s = b_in[tid];
            #pragma unroll 8
            for (int c = 0; c < DIM; c++) s = fmaf(w_in[tid*DIM + c], xm[c], s);
            g0[tid] = s;   // spatial mean of h (mean is linear)
        }
        __syncthreads();
        if (tid < HID) {
            float s = bg1[tid];
            #pragma unroll 8
            for (int c = 0; c < HID; c++) s = fmaf(wg1[tid*HID + c], g0[c], s);
            g1[tid] = s > 0.f ? s : 0.f;
        }
        __syncthreads();
        if (tid < HID) {
            #pragma unroll
            for (int tt = 0; tt < 9; tt++) {
                int row = tid*9 + tt;
                float s = bg2[row];
                #pragma unroll 8
                for (int c = 0; c < HID; c++) s = fmaf(wg2[row*HID + c], g1[c], s);
                g_ker[b*HID*9 + row] = s;
            }
        }
    }
    gbar(&g_bar2, NB, tid);

    // ============== one-time staging of weights + biases ====================
    for (int i = tid; i < HID*DIM; i += NT) {
        int o = i >> 6, c = i & 63;
        smem[OF_WINT + c*HID + o] = w_in[i];      // [c][hid]
    }
    for (int i = tid; i < 64*HID; i += NT) {
        int o = i >> 7, hid = i & 127;
        smem[OF_WOUT + hid*64 + o] = w_out[i];    // [hid][o]
    }
    if (tid < HID) smem[OF_BIN + tid]  = b_in[tid];
    if (tid < 64)  smem[OF_BOUT + tid] = b_out[tid];

    // ------------------- thread decodes -------------------
    // phase 1: 54 px-groups x 8 pairblocks (4 pairs each) = 432 jobs
    const int pxg = tid >> 3;             // 0..63 (54 used)
    const int pb  = tid & 7;              // 0..7
    const int px0 = pxg * 6;
    const bool p1act = (pxg < 54);
    // phase 2a: 128 px-pairs x 4 pair-groups
    const int lane2a = tid & 127;
    const int pg2a   = tid >> 7;          // 0..3
    const int px0a   = lane2a * 2;
    const int ctr2a  = ((px0a >> 4) + 1)*PAD + (px0a & 15) + 1;
    // phase 2b: 64 px-quads x 8 out-pair blocks (4 pairs each)
    const int pxq  = tid >> 3;            // 0..63
    const int ob   = tid & 7;             // 0..7
    const int px0b = pxq * 4;

    const ull ABSM = 0x7fffffff7fffffffULL;
    const ull C55 = pack2(0.55f), C45 = pack2(0.45f);

    #pragma unroll 1
    for (int t = blockIdx.x; t < NTILES; t += (int)NB) {
        const int b   = t / (NTILX*NTILY);
        const int r   = t - b*(NTILX*NTILY);
        const int ty0 = (r / NTILX)*TS;
        const int tx0 = (r % NTILX)*TS;
        const float* xb = x + (size_t)b * DIM * HW;

        __syncthreads();   // prior tile done reading sh_ker2 / sh_y / sh_h

        // restage this sample's paired kernels (only b-dependent smem data)
        {
            const float* kb = g_ker + b*HID*9;
            for (int i = tid; i < 64*9; i += NT) {
                int p = i / 9, tt = i - p*9;
                ((ull*)(smem + OF_KER2))[i] = pack2b(kb[(2*p)*9 + tt], kb[(2*p+1)*9 + tt]);
            }
        }

        #pragma unroll 1
        for (int hh = 0; hh < 2; hh++) {
            // ================= Phase 1: h half (32 pairs) =================
            ull acc[6][4];
            {
                const ull* bp = (const ull*)(smem + OF_BIN) + hh*32 + pb*4;
                #pragma unroll
                for (int j = 0; j < 4; j++) {
                    ull bj = bp[j];
                    #pragma unroll
                    for (int k = 0; k < 6; k++) acc[k][j] = bj;
                }
            }

            #pragma unroll 1
            for (int cc = 0; cc < 2; cc++) {
                __syncthreads();   // prior sh_x readers done (also orders ker2)
                // stage x chunk [32c][324px] with border zeros
                for (int i = tid; i < 32*NPIX; i += NT) {
                    int c  = i / NPIX, pp = i - c*NPIX;
                    int py = pp / PAD, pxx = pp - py*PAD;
                    int gy = ty0 + py - 1, gx = tx0 + pxx - 1;
                    float v = 0.f;
                    if ((gy >= 0) & (gy < HH) & (gx >= 0) & (gx < WW))
                        v = __ldg(xb + (size_t)(cc*32 + c)*HW + gy*WW + gx);
                    smem[OF_X + i] = v;
                }
                __syncthreads();

                if (p1act) {
                    #pragma unroll 2
                    for (int c = 0; c < 32; c++) {
                        const ulonglong2* wp = (const ulonglong2*)
                            ((const ull*)smem + (size_t)(cc*32 + c)*64 + hh*32 + pb*4);
                        ulonglong2 wA = wp[0], wB = wp[1];
                        const float* xs = smem + OF_X + c*NPIX + px0;
                        #pragma unroll
                        for (int k = 0; k < 6; k++) {
                            ull xx = pack2(xs[k]);
                            acc[k][0] = ffma2(wA.x, xx, acc[k][0]);
                            acc[k][1] = ffma2(wA.y, xx, acc[k][1]);
                            acc[k][2] = ffma2(wB.x, xx, acc[k][2]);
                            acc[k][3] = ffma2(wB.y, xx, acc[k][3]);
                        }
                    }
                }
            }

            // store h half (zero-masked at borders)
            if (p1act) {
                #pragma unroll
                for (int k = 0; k < 6; k++) {
                    int pp = px0 + k;
                    int py = pp / PAD, pxx = pp - py*PAD;
                    int gy = ty0 + py - 1, gx = tx0 + pxx - 1;
                    bool v = (gy >= 0) & (gy < HH) & (gx >= 0) & (gx < WW);
                    ull* hd = (ull*)(smem + OF_H) + pb*4*NPIX + pp;
                    #pragma unroll
                    for (int j = 0; j < 4; j++)
                        hd[j*NPIX] = v ? acc[k][j] : 0ull;
                }
            }
            __syncthreads();

            // ================= Phase 2: dw + leaky + projection ============
            ull pacc[4][4];
            if (hh == 0) {
                const ull* bop = (const ull*)(smem + OF_BOUT) + ob*4;
                #pragma unroll
                for (int j = 0; j < 4; j++) {
                    ull bj = bop[j];
                    #pragma unroll
                    for (int k = 0; k < 4; k++) pacc[k][j] = bj;
                }
            } else {
                #pragma unroll
                for (int j = 0; j < 4; j++)
                    #pragma unroll
                    for (int k = 0; k < 4; k++) pacc[k][j] = 0ull;
            }

            #pragma unroll 1
            for (int yc = 0; yc < 32; yc += 8) {
                // 2a: dw 3x3 + LeakyReLU for 8 pairs, 2 px per thread, 2 slots
                #pragma unroll
                for (int s = 0; s < 2; s++) {
                    int p_rel = yc + pg2a*2 + s;
                    int gp = hh*32 + p_rel;
                    const ull* hp = (const ull*)(smem + OF_H) + p_rel*NPIX + ctr2a;
                    const ull* kp = (const ull*)(smem + OF_KER2) + gp*9;
                    ull k0 = kp[0], k1 = kp[1], k2 = kp[2], k3 = kp[3], k4 = kp[4],
                        k5 = kp[5], k6 = kp[6], k7 = kp[7], k8 = kp[8];
                    ull a0 = hp[-PAD-1], a1 = hp[-PAD], a2 = hp[-PAD+1], a3 = hp[-PAD+2];
                    ull b0 = hp[-1],     b1 = hp[0],    b2 = hp[1],      b3 = hp[2];
                    ull c0 = hp[PAD-1],  c1 = hp[PAD],  c2 = hp[PAD+1],  c3 = hp[PAD+2];
                    ull sA = mul2(k0, a0);
                    sA = ffma2(k1, a1, sA); sA = ffma2(k2, a2, sA);
                    sA = ffma2(k3, b0, sA); sA = ffma2(k4, b1, sA); sA = ffma2(k5, b2, sA);
                    sA = ffma2(k6, c0, sA); sA = ffma2(k7, c1, sA); sA = ffma2(k8, c2, sA);
                    ull sB = mul2(k0, a1);
                    sB = ffma2(k1, a2, sB); sB = ffma2(k2, a3, sB);
                    sB = ffma2(k3, b1, sB); sB = ffma2(k4, b2, sB); sB = ffma2(k5, b3, sB);
                    sB = ffma2(k6, c1, sB); sB = ffma2(k7, c2, sB); sB = ffma2(k8, c3, sB);
                    // LeakyReLU(0.1): 0.55*s + 0.45*|s|
                    ulonglong2 yv2;
                    yv2.x = ffma2(sA & ABSM, C45, mul2(sA, C55));
                    yv2.y = ffma2(sB & ABSM, C45, mul2(sB, C55));
                    *(ulonglong2*)((ull*)(smem + OF_Y) + (p_rel - yc)*256 + px0a) = yv2;
                }
                __syncthreads();

                // 2b: projection, 4 px x 4 out-pairs per thread
                #pragma unroll 1
                for (int p = 0; p < 8; p++) {
                    int gp = hh*32 + yc + p;
                    const ulonglong2* yp =
                        (const ulonglong2*)((const ull*)(smem + OF_Y) + p*256 + px0b);
                    ulonglong2 y01 = yp[0], y23 = yp[1];
                    const ull* wbase = (const ull*)(smem + OF_WOUT);
                    const ulonglong2* wl =
                        (const ulonglong2*)(wbase + (size_t)(2*gp)*32 + ob*4);
                    const ulonglong2* wh =
                        (const ulonglong2*)(wbase + (size_t)(2*gp)*32 + 32 + ob*4);
                    ulonglong2 l01 = wl[0], l23 = wl[1];
                    ulonglong2 h01 = wh[0], h23 = wh[1];
                    ull wlo[4] = {l01.x, l01.y, l23.x, l23.y};
                    ull whi[4] = {h01.x, h01.y, h23.x, h23.y};
                    ull yv[4] = {y01.x, y01.y, y23.x, y23.y};
                    #pragma unroll
                    for (int k = 0; k < 4; k++) {
                        float ylo, yhi;
                        unpack2(yv[k], ylo, yhi);
                        ull ylo2 = pack2(ylo), yhi2 = pack2(yhi);
                        #pragma unroll
                        for (int j = 0; j < 4; j++) {
                            pacc[k][j] = ffma2(wlo[j], ylo2, pacc[k][j]);
                            pacc[k][j] = ffma2(whi[j], yhi2, pacc[k][j]);
                        }
                    }
                }
                __syncthreads();   // before next yc overwrites sh_y
            }

            // accumulate halves through gmem: hh=0 store, hh=1 read-add-write
            {
                const int gy = ty0 + (px0b >> 4), gx = tx0 + (px0b & 15);
                float* op = out + (size_t)b * DIM * HW + (size_t)gy*WW + gx;
                #pragma unroll
                for (int j = 0; j < 4; j++) {
                    float l0, h0, l1, h1, l2, h2, l3, h3;
                    unpack2(pacc[0][j], l0, h0);
                    unpack2(pacc[1][j], l1, h1);
                    unpack2(pacc[2][j], l2, h2);
                    unpack2(pacc[3][j], l3, h3);
                    float4 vlo = {l0, l1, l2, l3};
                    float4 vhi = {h0, h1, h2, h3};
                    float4* plo = (float4*)(op + (size_t)(ob*8 + 2*j)*HW);
                    float4* phi = (float4*)(op + (size_t)(ob*8 + 2*j + 1)*HW);
                    if (hh == 0) {
                        *plo = vlo;
                        *phi = vhi;
                    } else {
                        float4 rl = *plo, rh = *phi;
                        rl.x += vlo.x; rl.y += vlo.y; rl.z += vlo.z; rl.w += vlo.w;
                        rh.x += vhi.x; rh.y += vhi.y; rh.z += vhi.z; rh.w += vhi.w;
                        *plo = rl;
                        *phi = rh;
                    }
                }
            }
        } // hh
    } // tiles

    // reset barrier state for the next graph replay
    if (tid == 0) {
        __threadfence();
        if (atomicAdd(&g_done, 1u) == NB - 1u) {
            atomicExch(&g_bar1, 0u);
            atomicExch(&g_bar2, 0u);
            atomicExch(&g_done, 0u);
        }
    }
}

// ---------------------------------------------------------------------------
extern "C" void kernel_launch(void* const* d_in, const int* in_sizes, int n_in,
                              void* d_out, int out_size) {
    const float* x     = (const float*)d_in[0];
    const float* w_in  = (const float*)d_in[1];
    const float* b_in  = (const float*)d_in[2];
    const float* wg1   = (const float*)d_in[3];
    const float* bg1   = (const float*)d_in[4];
    const float* wg2   = (const float*)d_in[5];
    const float* bg2   = (const float*)d_in[6];
    const float* w_out = (const float*)d_in[7];
    const float* b_out = (const float*)d_in[8];
    float* out = (float*)d_out;

    int dev = 0, nsm = 148;
    cudaGetDevice(&dev);
    cudaDeviceGetAttribute(&nsm, cudaDevAttrMultiProcessorCount, dev);

    const int SMEM_BYTES = SM_FLOATS * 4;   // 211,712 B
    cudaFuncSetAttribute(k_all, cudaFuncAttributeMaxDynamicSharedMemorySize, SMEM_BYTES);

    k_all<<<nsm, NT, SMEM_BYTES>>>(x, w_in, b_in, wg1, bg1, wg2, bg2, w_out, b_out, out);
}